// round 3
// baseline (speedup 1.0000x reference)
#include <cuda_runtime.h>
#include <cuda_fp16.h>
#include <cstdint>

// Problem constants
#define B_   4
#define N_   4096
#define C_   128
#define H_   4
#define D_   32
#define BH_  (B_*H_)           // 16
#define QK_ELEMS (BH_*N_*D_)   // 2,097,152

// ---------------- static scratch (no allocs allowed) ----------------
__device__ float  g_Qf[QK_ELEMS];
__device__ float  g_Kf[QK_ELEMS];
__device__ __half g_Qh[QK_ELEMS];
__device__ __half g_Kh[QK_ELEMS];
__device__ __half g_Vh[QK_ELEMS];
__device__ float  g_Of[B_*N_*C_];      // attention output [b][n][h*32+d]
__device__ float  g_qinv[BH_*D_];      // 10 / norm
__device__ float  g_kinv[BH_*D_];      // 1 / norm

// =====================================================================
// Kernel 1: QKV GEMM  (X[16384,128] @ W[128,384]) fp32, epilogue routes
// q->g_Qf, k->g_Kf, v->g_Vh  in [bh][n][d] layout.
// =====================================================================
__global__ __launch_bounds__(256) void gemm_qkv_kernel(
    const float* __restrict__ X, const float* __restrict__ W)
{
    __shared__ float As[16][64];   // [k][m]
    __shared__ float Bs[16][64];   // [k][n]
    const int tid = threadIdx.x;
    const int m0 = blockIdx.y * 64;
    const int n0 = blockIdx.x * 64;
    const int tm = (tid >> 4) * 4;
    const int tn = (tid & 15) * 4;

    float acc[4][4];
    #pragma unroll
    for (int i = 0; i < 4; i++)
        #pragma unroll
        for (int j = 0; j < 4; j++) acc[i][j] = 0.f;

    for (int kb = 0; kb < 128; kb += 16) {
        {   // X tile -> As (transposed)
            int r = tid >> 2, c = (tid & 3) * 4;
            float4 v = *(const float4*)&X[(m0 + r) * 128 + kb + c];
            As[c + 0][r] = v.x; As[c + 1][r] = v.y;
            As[c + 2][r] = v.z; As[c + 3][r] = v.w;
            // W tile -> Bs
            int rk = tid >> 4, cn = (tid & 15) * 4;
            *(float4*)&Bs[rk][cn] = *(const float4*)&W[(kb + rk) * 384 + n0 + cn];
        }
        __syncthreads();
        #pragma unroll
        for (int kk = 0; kk < 16; kk++) {
            float a[4], b[4];
            #pragma unroll
            for (int i = 0; i < 4; i++) a[i] = As[kk][tm + i];
            #pragma unroll
            for (int j = 0; j < 4; j++) b[j] = Bs[kk][tn + j];
            #pragma unroll
            for (int i = 0; i < 4; i++)
                #pragma unroll
                for (int j = 0; j < 4; j++) acc[i][j] += a[i] * b[j];
        }
        __syncthreads();
    }

    // epilogue: route q/k/v.  tn multiple of 4 => 4 consecutive cols stay in one head
    #pragma unroll
    for (int i = 0; i < 4; i++) {
        int m = m0 + tm + i;
        int b = m >> 12, n = m & 4095;
        int e0 = n0 + tn;                 // first of 4 consecutive output cols
        int ec = e0 & 127;                // channel within q/k/v
        int h = ec >> 5, d = ec & 31;
        int idx = ((b * 4 + h) * 4096 + n) * 32 + d;
        if (e0 < 128) {
            *(float4*)&g_Qf[idx] = make_float4(acc[i][0], acc[i][1], acc[i][2], acc[i][3]);
        } else if (e0 < 256) {
            *(float4*)&g_Kf[idx] = make_float4(acc[i][0], acc[i][1], acc[i][2], acc[i][3]);
        } else {
            g_Vh[idx + 0] = __float2half(acc[i][0]);
            g_Vh[idx + 1] = __float2half(acc[i][1]);
            g_Vh[idx + 2] = __float2half(acc[i][2]);
            g_Vh[idx + 3] = __float2half(acc[i][3]);
        }
    }
}

// =====================================================================
// Kernel 2: column sum-of-squares over N per (bh,d), for q and k.
// grid = 32 blocks (16 bh x {q,k}), 256 threads = 8 groups x 32 d.
// =====================================================================
__global__ __launch_bounds__(256) void colnorm_kernel()
{
    const int bh = blockIdx.x & 15;
    const int which = blockIdx.x >> 4;     // 0 = q, 1 = k
    const float* src = (which ? g_Kf : g_Qf) + bh * N_ * D_;
    const int d = threadIdx.x & 31;
    const int grp = threadIdx.x >> 5;      // 0..7

    float s = 0.f;
    for (int n = grp; n < N_; n += 8) {
        float v = src[n * 32 + d];
        s += v * v;
    }
    __shared__ float red[256];
    red[threadIdx.x] = s;
    __syncthreads();
    if (threadIdx.x < 32) {
        float tot = 0.f;
        #pragma unroll
        for (int g = 0; g < 8; g++) tot += red[g * 32 + d];
        float nrm = fmaxf(sqrtf(tot), 1e-12f);
        if (which) g_kinv[bh * 32 + d] = 1.0f / nrm;
        else       g_qinv[bh * 32 + d] = 10.0f / nrm;   // fold SCALE into Q
    }
}

// =====================================================================
// Kernel 3: normalize + convert to fp16
// =====================================================================
__global__ __launch_bounds__(256) void normalize_kernel()
{
    int i = blockIdx.x * 256 + threadIdx.x;   // 0 .. QK_ELEMS-1
    int col = ((i >> 17) << 5) | (i & 31);    // bh*32 + d   (4096*32 = 1<<17)
    g_Qh[i] = __float2half(g_Qf[i] * g_qinv[col]);
    g_Kh[i] = __float2half(g_Kf[i] * g_kinv[col]);
}

// =====================================================================
// Kernel 4: flash attention, fp16 mma.m16n8k16, fp32 accum.
// grid (64 q-tiles, 16 bh), 128 threads (4 warps x m16 rows).
// =====================================================================
#define MMA16816(d0,d1,d2,d3, a0,a1,a2,a3, b0,b1)                               \
    asm volatile("mma.sync.aligned.m16n8k16.row.col.f32.f16.f16.f32 "          \
        "{%0,%1,%2,%3}, {%4,%5,%6,%7}, {%8,%9}, {%0,%1,%2,%3};\n"              \
        : "+f"(d0), "+f"(d1), "+f"(d2), "+f"(d3)                                \
        : "r"(a0), "r"(a1), "r"(a2), "r"(a3), "r"(b0), "r"(b1))

__device__ __forceinline__ unsigned pack_h2(float x, float y) {
    __half2 h = __float22half2_rn(make_float2(x, y));
    return *reinterpret_cast<unsigned*>(&h);
}

__global__ __launch_bounds__(128) void flash_kernel()
{
    const int qt   = blockIdx.x;      // 0..63
    const int bh   = blockIdx.y;      // 0..15
    const int tid  = threadIdx.x;
    const int lane = tid & 31;
    const int warp = tid >> 5;
    const int g    = lane >> 2;       // 0..7
    const int q2   = (lane & 3) * 2;  // 0,2,4,6

    __shared__ __align__(16) __half Qs[64][40];
    __shared__ __align__(16) __half Ks[64][40];
    __shared__ __align__(16) __half Vt[32][72];

    const __half* Qg = g_Qh + (bh * N_ + qt * 64) * 32;
    const __half* Kg = g_Kh + bh * N_ * 32;
    const __half* Vg = g_Vh + bh * N_ * 32;

    // stage Q tile (64 x 32 halves)
    {
        const int4* src = (const int4*)Qg;
        #pragma unroll
        for (int i = tid; i < 256; i += 128) {
            int4 v = src[i];
            *(int4*)&Qs[i >> 2][(i & 3) * 8] = v;
        }
    }
    __syncthreads();

    // Q fragments (A operand), kept in registers for the whole loop
    unsigned qa[2][4];
    const int rb = warp * 16;
    #pragma unroll
    for (int kc = 0; kc < 2; kc++) {
        int d0 = kc * 16;
        qa[kc][0] = *(const unsigned*)&Qs[rb + g][d0 + q2];
        qa[kc][1] = *(const unsigned*)&Qs[rb + 8 + g][d0 + q2];
        qa[kc][2] = *(const unsigned*)&Qs[rb + g][d0 + 8 + q2];
        qa[kc][3] = *(const unsigned*)&Qs[rb + 8 + g][d0 + 8 + q2];
    }

    float o[4][4];
    #pragma unroll
    for (int t = 0; t < 4; t++)
        #pragma unroll
        for (int r = 0; r < 4; r++) o[t][r] = 0.f;
    float m0 = -1e30f, m1 = -1e30f, l0 = 0.f, l1 = 0.f;

    for (int kb = 0; kb < 64; kb++) {
        __syncthreads();   // previous iteration's reads done
        {
            const int4* src = (const int4*)(Kg + kb * 64 * 32);
            #pragma unroll
            for (int i = tid; i < 256; i += 128) {
                int4 v = src[i];
                *(int4*)&Ks[i >> 2][(i & 3) * 8] = v;
            }
            const __half2* vsrc = (const __half2*)(Vg + kb * 64 * 32);
            #pragma unroll
            for (int i = tid; i < 1024; i += 128) {
                __half2 v = vsrc[i];
                int j = i >> 4, d = (i & 15) * 2;
                Vt[d][j]     = __low2half(v);
                Vt[d + 1][j] = __high2half(v);
            }
        }
        __syncthreads();

        // ---- S = Q K^T  (16 x 64 per warp) ----
        float s[8][4];
        #pragma unroll
        for (int t = 0; t < 8; t++)
            #pragma unroll
            for (int r = 0; r < 4; r++) s[t][r] = 0.f;

        #pragma unroll
        for (int t = 0; t < 8; t++) {
            #pragma unroll
            for (int kc = 0; kc < 2; kc++) {
                int d0 = kc * 16;
                unsigned b0 = *(const unsigned*)&Ks[t * 8 + g][d0 + q2];
                unsigned b1 = *(const unsigned*)&Ks[t * 8 + g][d0 + 8 + q2];
                MMA16816(s[t][0], s[t][1], s[t][2], s[t][3],
                         qa[kc][0], qa[kc][1], qa[kc][2], qa[kc][3], b0, b1);
            }
        }

        // ---- online softmax ----
        float mx0 = -1e30f, mx1 = -1e30f;
        #pragma unroll
        for (int t = 0; t < 8; t++) {
            mx0 = fmaxf(mx0, fmaxf(s[t][0], s[t][1]));
            mx1 = fmaxf(mx1, fmaxf(s[t][2], s[t][3]));
        }
        mx0 = fmaxf(mx0, __shfl_xor_sync(0xffffffffu, mx0, 1));
        mx0 = fmaxf(mx0, __shfl_xor_sync(0xffffffffu, mx0, 2));
        mx1 = fmaxf(mx1, __shfl_xor_sync(0xffffffffu, mx1, 1));
        mx1 = fmaxf(mx1, __shfl_xor_sync(0xffffffffu, mx1, 2));

        float nm0 = fmaxf(m0, mx0), nm1 = fmaxf(m1, mx1);
        float c0 = __expf(m0 - nm0), c1 = __expf(m1 - nm1);
        m0 = nm0; m1 = nm1;

        float rs0 = 0.f, rs1 = 0.f;
        #pragma unroll
        for (int t = 0; t < 8; t++) {
            s[t][0] = __expf(s[t][0] - m0);
            s[t][1] = __expf(s[t][1] - m0);
            s[t][2] = __expf(s[t][2] - m1);
            s[t][3] = __expf(s[t][3] - m1);
            rs0 += s[t][0] + s[t][1];
            rs1 += s[t][2] + s[t][3];
        }
        rs0 += __shfl_xor_sync(0xffffffffu, rs0, 1);
        rs0 += __shfl_xor_sync(0xffffffffu, rs0, 2);
        rs1 += __shfl_xor_sync(0xffffffffu, rs1, 1);
        rs1 += __shfl_xor_sync(0xffffffffu, rs1, 2);
        l0 = l0 * c0 + rs0;
        l1 = l1 * c1 + rs1;

        #pragma unroll
        for (int t = 0; t < 4; t++) {
            o[t][0] *= c0; o[t][1] *= c0;
            o[t][2] *= c1; o[t][3] *= c1;
        }

        // ---- O += P V  (16 x 32 per warp) ----
        #pragma unroll
        for (int jc = 0; jc < 4; jc++) {
            unsigned pa0 = pack_h2(s[2 * jc][0],     s[2 * jc][1]);
            unsigned pa1 = pack_h2(s[2 * jc][2],     s[2 * jc][3]);
            unsigned pa2 = pack_h2(s[2 * jc + 1][0], s[2 * jc + 1][1]);
            unsigned pa3 = pack_h2(s[2 * jc + 1][2], s[2 * jc + 1][3]);
            int j0 = jc * 16;
            #pragma unroll
            for (int t = 0; t < 4; t++) {
                unsigned b0 = *(const unsigned*)&Vt[t * 8 + g][j0 + q2];
                unsigned b1 = *(const unsigned*)&Vt[t * 8 + g][j0 + 8 + q2];
                MMA16816(o[t][0], o[t][1], o[t][2], o[t][3],
                         pa0, pa1, pa2, pa3, b0, b1);
            }
        }
    }

    // ---- finalize: divide by l, write to g_Of [b][n][h*32+d] ----
    float inv0 = 1.0f / l0, inv1 = 1.0f / l1;
    int b = bh >> 2, h = bh & 3;
    int r0 = qt * 64 + rb + g;
    float* dst0 = g_Of + (b * N_ + r0) * 128 + h * 32;
    float* dst1 = dst0 + 8 * 128;
    #pragma unroll
    for (int t = 0; t < 4; t++) {
        int d = t * 8 + q2;
        *(float2*)&dst0[d] = make_float2(o[t][0] * inv0, o[t][1] * inv0);
        *(float2*)&dst1[d] = make_float2(o[t][2] * inv1, o[t][3] * inv1);
    }
}

// =====================================================================
// Kernel 5: output projection  (Of[16384,128] @ Wout[128,128]) + bias
// =====================================================================
__global__ __launch_bounds__(256) void gemm_out_kernel(
    const float* __restrict__ W, const float* __restrict__ bias,
    float* __restrict__ out)
{
    __shared__ float As[16][64];
    __shared__ float Bs[16][64];
    const int tid = threadIdx.x;
    const int m0 = blockIdx.y * 64;
    const int n0 = blockIdx.x * 64;
    const int tm = (tid >> 4) * 4;
    const int tn = (tid & 15) * 4;

    float acc[4][4];
    #pragma unroll
    for (int i = 0; i < 4; i++)
        #pragma unroll
        for (int j = 0; j < 4; j++) acc[i][j] = 0.f;

    for (int kb = 0; kb < 128; kb += 16) {
        {
            int r = tid >> 2, c = (tid & 3) * 4;
            float4 v = *(const float4*)&g_Of[(m0 + r) * 128 + kb + c];
            As[c + 0][r] = v.x; As[c + 1][r] = v.y;
            As[c + 2][r] = v.z; As[c + 3][r] = v.w;
            int rk = tid >> 4, cn = (tid & 15) * 4;
            *(float4*)&Bs[rk][cn] = *(const float4*)&W[(kb + rk) * 128 + n0 + cn];
        }
        __syncthreads();
        #pragma unroll
        for (int kk = 0; kk < 16; kk++) {
            float a[4], b[4];
            #pragma unroll
            for (int i = 0; i < 4; i++) a[i] = As[kk][tm + i];
            #pragma unroll
            for (int j = 0; j < 4; j++) b[j] = Bs[kk][tn + j];
            #pragma unroll
            for (int i = 0; i < 4; i++)
                #pragma unroll
                for (int j = 0; j < 4; j++) acc[i][j] += a[i] * b[j];
        }
        __syncthreads();
    }

    float4 bv = *(const float4*)&bias[n0 + tn];
    #pragma unroll
    for (int i = 0; i < 4; i++) {
        int m = m0 + tm + i;
        *(float4*)&out[m * 128 + n0 + tn] =
            make_float4(acc[i][0] + bv.x, acc[i][1] + bv.y,
                        acc[i][2] + bv.z, acc[i][3] + bv.w);
    }
}

// =====================================================================
extern "C" void kernel_launch(void* const* d_in, const int* in_sizes, int n_in,
                              void* d_out, int out_size)
{
    const float* x     = (const float*)d_in[0];   // [4,4096,128]
    const float* Wqkv  = (const float*)d_in[1];   // [128,384]
    const float* Wout  = (const float*)d_in[2];   // [128,128]
    const float* bout  = (const float*)d_in[3];   // [128]
    float* out = (float*)d_out;                   // [4,4096,128]

    gemm_qkv_kernel<<<dim3(6, 256), 256>>>(x, Wqkv);
    colnorm_kernel<<<32, 256>>>();
    normalize_kernel<<<QK_ELEMS / 256, 256>>>();
    flash_kernel<<<dim3(64, 16), 128>>>();
    gemm_out_kernel<<<dim3(2, 256), 256>>>(Wout, bout, out);
}

// round 4
// speedup vs baseline: 1.3864x; 1.3864x over previous
#include <cuda_runtime.h>
#include <cuda_fp16.h>
#include <cstdint>

// Problem constants
#define B_   4
#define N_   4096
#define C_   128
#define H_   4
#define D_   32
#define BH_  (B_*H_)           // 16
#define QK_ELEMS (BH_*N_*D_)   // 2,097,152

// ---------------- static scratch (no allocs allowed) ----------------
__device__ float  g_Qf[QK_ELEMS];
__device__ float  g_Kf[QK_ELEMS];
__device__ __half g_Qh[QK_ELEMS];
__device__ __half g_Kh[QK_ELEMS];
__device__ __half g_Vh[QK_ELEMS];
__device__ float  g_Of[B_*N_*C_];      // attention output [b][n][h*32+d]
__device__ float  g_qinv[BH_*D_];      // 10 / norm
__device__ float  g_kinv[BH_*D_];      // 1 / norm

// =====================================================================
// Kernel 1: QKV GEMM  (X[16384,128] @ W[128,384]) fp32, epilogue routes
// q->g_Qf, k->g_Kf, v->g_Vh  in [bh][n][d] layout.
// =====================================================================
__global__ __launch_bounds__(256) void gemm_qkv_kernel(
    const float* __restrict__ X, const float* __restrict__ W)
{
    __shared__ float As[16][64];   // [k][m]
    __shared__ float Bs[16][64];   // [k][n]
    const int tid = threadIdx.x;
    const int m0 = blockIdx.y * 64;
    const int n0 = blockIdx.x * 64;
    const int tm = (tid >> 4) * 4;
    const int tn = (tid & 15) * 4;

    float acc[4][4];
    #pragma unroll
    for (int i = 0; i < 4; i++)
        #pragma unroll
        for (int j = 0; j < 4; j++) acc[i][j] = 0.f;

    for (int kb = 0; kb < 128; kb += 16) {
        {   // X tile -> As (transposed)
            int r = tid >> 2, c = (tid & 3) * 4;
            float4 v = *(const float4*)&X[(m0 + r) * 128 + kb + c];
            As[c + 0][r] = v.x; As[c + 1][r] = v.y;
            As[c + 2][r] = v.z; As[c + 3][r] = v.w;
            // W tile -> Bs
            int rk = tid >> 4, cn = (tid & 15) * 4;
            *(float4*)&Bs[rk][cn] = *(const float4*)&W[(kb + rk) * 384 + n0 + cn];
        }
        __syncthreads();
        #pragma unroll
        for (int kk = 0; kk < 16; kk++) {
            float a[4], b[4];
            #pragma unroll
            for (int i = 0; i < 4; i++) a[i] = As[kk][tm + i];
            #pragma unroll
            for (int j = 0; j < 4; j++) b[j] = Bs[kk][tn + j];
            #pragma unroll
            for (int i = 0; i < 4; i++)
                #pragma unroll
                for (int j = 0; j < 4; j++) acc[i][j] += a[i] * b[j];
        }
        __syncthreads();
    }

    // epilogue: route q/k/v.  tn multiple of 4 => 4 consecutive cols stay in one head
    #pragma unroll
    for (int i = 0; i < 4; i++) {
        int m = m0 + tm + i;
        int b = m >> 12, n = m & 4095;
        int e0 = n0 + tn;                 // first of 4 consecutive output cols
        int ec = e0 & 127;                // channel within q/k/v
        int h = ec >> 5, d = ec & 31;
        int idx = ((b * 4 + h) * 4096 + n) * 32 + d;
        if (e0 < 128) {
            *(float4*)&g_Qf[idx] = make_float4(acc[i][0], acc[i][1], acc[i][2], acc[i][3]);
        } else if (e0 < 256) {
            *(float4*)&g_Kf[idx] = make_float4(acc[i][0], acc[i][1], acc[i][2], acc[i][3]);
        } else {
            g_Vh[idx + 0] = __float2half(acc[i][0]);
            g_Vh[idx + 1] = __float2half(acc[i][1]);
            g_Vh[idx + 2] = __float2half(acc[i][2]);
            g_Vh[idx + 3] = __float2half(acc[i][3]);
        }
    }
}

// =====================================================================
// Kernel 2: column sum-of-squares over N per (bh,d), for q and k.
// =====================================================================
__global__ __launch_bounds__(256) void colnorm_kernel()
{
    const int bh = blockIdx.x & 15;
    const int which = blockIdx.x >> 4;     // 0 = q, 1 = k
    const float* src = (which ? g_Kf : g_Qf) + bh * N_ * D_;
    const int d = threadIdx.x & 31;
    const int grp = threadIdx.x >> 5;      // 0..7

    float s = 0.f;
    for (int n = grp; n < N_; n += 8) {
        float v = src[n * 32 + d];
        s += v * v;
    }
    __shared__ float red[256];
    red[threadIdx.x] = s;
    __syncthreads();
    if (threadIdx.x < 32) {
        float tot = 0.f;
        #pragma unroll
        for (int g = 0; g < 8; g++) tot += red[g * 32 + d];
        float nrm = fmaxf(sqrtf(tot), 1e-12f);
        if (which) g_kinv[bh * 32 + d] = 1.0f / nrm;
        else       g_qinv[bh * 32 + d] = 10.0f / nrm;   // fold SCALE into Q
    }
}

// =====================================================================
// Kernel 3: normalize + convert to fp16
// =====================================================================
__global__ __launch_bounds__(256) void normalize_kernel()
{
    int i = blockIdx.x * 256 + threadIdx.x;   // 0 .. QK_ELEMS-1
    int col = ((i >> 17) << 5) | (i & 31);    // bh*32 + d   (4096*32 = 1<<17)
    g_Qh[i] = __float2half(g_Qf[i] * g_qinv[col]);
    g_Kh[i] = __float2half(g_Kf[i] * g_kinv[col]);
}

// =====================================================================
// Kernel 4: flash attention, fp16 mma.m16n8k16, fp32 accum.
// Br=128 (8 warps x 16 rows), Bc=64, cp.async double-buffered K/V,
// ldmatrix fragment loads, no online-max (logits bounded ~0.1).
// grid (32 q-tiles, 16 bh), 256 threads.
// =====================================================================
#define MMA16816(d, a, b0, b1)                                                  \
    asm volatile("mma.sync.aligned.m16n8k16.row.col.f32.f16.f16.f32 "          \
        "{%0,%1,%2,%3}, {%4,%5,%6,%7}, {%8,%9}, {%0,%1,%2,%3};\n"              \
        : "+f"(d[0]), "+f"(d[1]), "+f"(d[2]), "+f"(d[3])                        \
        : "r"(a[0]), "r"(a[1]), "r"(a[2]), "r"(a[3]), "r"(b0), "r"(b1))

#define LDMX4(r0,r1,r2,r3,addr)                                                 \
    asm volatile("ldmatrix.sync.aligned.m8n8.x4.shared.b16 {%0,%1,%2,%3}, [%4];\n" \
        : "=r"(r0), "=r"(r1), "=r"(r2), "=r"(r3) : "r"(addr))

#define LDMX4T(r0,r1,r2,r3,addr)                                                \
    asm volatile("ldmatrix.sync.aligned.m8n8.x4.trans.shared.b16 {%0,%1,%2,%3}, [%4];\n" \
        : "=r"(r0), "=r"(r1), "=r"(r2), "=r"(r3) : "r"(addr))

__device__ __forceinline__ void cp16(uint32_t dst, const void* src) {
    asm volatile("cp.async.cg.shared.global [%0], [%1], 16;\n" :: "r"(dst), "l"(src));
}
#define CP_COMMIT() asm volatile("cp.async.commit_group;\n" ::: "memory")
#define CP_WAIT1()  asm volatile("cp.async.wait_group 1;\n" ::: "memory")

__device__ __forceinline__ unsigned pack_h2(float x, float y) {
    __half2 h = __float22half2_rn(make_float2(x, y));
    return *reinterpret_cast<unsigned*>(&h);
}

#define PITCH     40                    // halves per smem row (80B, 16B aligned, LDSM conflict-free)
#define KV_BYTES  (64 * PITCH * 2)      // bytes per K or V stage

__global__ __launch_bounds__(256) void flash_kernel()
{
    const int qt   = blockIdx.x;      // 0..31  (128 q rows each)
    const int bh   = blockIdx.y;      // 0..15
    const int tid  = threadIdx.x;
    const int lane = tid & 31;
    const int warp = tid >> 5;        // 0..7
    const int g    = lane >> 2;       // 0..7
    const int q2   = (lane & 3) * 2;  // 0,2,4,6

    __shared__ __align__(16) __half Qs[128][PITCH];
    __shared__ __align__(16) __half Ks[2][64][PITCH];
    __shared__ __align__(16) __half Vs[2][64][PITCH];

    const __half* Qg = g_Qh + (bh * N_ + qt * 128) * 32;
    const __half* Kg = g_Kh + bh * N_ * 32;
    const __half* Vg = g_Vh + bh * N_ * 32;

    const uint32_t qs_base = (uint32_t)__cvta_generic_to_shared(&Qs[0][0]);
    const uint32_t ks_base = (uint32_t)__cvta_generic_to_shared(&Ks[0][0][0]);
    const uint32_t vs_base = (uint32_t)__cvta_generic_to_shared(&Vs[0][0][0]);

    // cp.async chunk assignment: 256 chunks (64 rows x 4 x 16B) per tile, 1/thread
    const int crow = tid >> 2;            // 0..63
    const int ccol = (tid & 3) * 8;       // halves: 0,8,16,24
    const uint32_t cdst = (uint32_t)(crow * (PITCH * 2) + ccol * 2);
    const int     csrc  = crow * 32 + ccol;

    // prefetch tile 0
    cp16(ks_base + cdst, Kg + csrc);
    cp16(vs_base + cdst, Vg + csrc);
    CP_COMMIT();

    // stage Q (128 x 32 halves = 512 int4 chunks) while tile 0 streams
    {
        const int4* src = (const int4*)Qg;
        #pragma unroll
        for (int i = tid; i < 512; i += 256) {
            int4 v = src[i];
            *(int4*)&Qs[i >> 2][(i & 3) * 8] = v;
        }
    }
    __syncthreads();

    // Q A-fragments, registers for the whole loop
    unsigned qa[2][4];
    const int rb = warp * 16;
    #pragma unroll
    for (int kc = 0; kc < 2; kc++) {
        uint32_t addr = qs_base +
            (uint32_t)(((rb + (lane & 15)) * PITCH + kc * 16 + (lane >> 4) * 8) * 2);
        LDMX4(qa[kc][0], qa[kc][1], qa[kc][2], qa[kc][3], addr);
    }

    float o[4][4];
    #pragma unroll
    for (int t = 0; t < 4; t++)
        #pragma unroll
        for (int r = 0; r < 4; r++) o[t][r] = 0.f;
    float l0 = 0.f, l1 = 0.f;

    for (int kb = 0; kb < 64; kb++) {
        const int st = kb & 1;
        if (kb + 1 < 64) {
            uint32_t off = (uint32_t)((st ^ 1) * KV_BYTES) + cdst;
            int s2 = (kb + 1) * 64 * 32 + csrc;
            cp16(ks_base + off, Kg + s2);
            cp16(vs_base + off, Vg + s2);
        }
        CP_COMMIT();
        CP_WAIT1();          // tile kb arrived (kb+1 still in flight)
        __syncthreads();

        const uint32_t kbase = ks_base + st * KV_BYTES;
        const uint32_t vbase = vs_base + st * KV_BYTES;

        // ---- S = Q K^T  (16 x 64 per warp) ----
        float s[8][4];
        #pragma unroll
        for (int t = 0; t < 8; t++) {
            unsigned b0, b1, b2, b3;
            uint32_t addr = kbase +
                (uint32_t)(((t * 8 + (lane & 7)) * PITCH + (lane >> 3) * 8) * 2);
            LDMX4(b0, b1, b2, b3, addr);
            s[t][0] = s[t][1] = s[t][2] = s[t][3] = 0.f;
            MMA16816(s[t], qa[0], b0, b1);
            MMA16816(s[t], qa[1], b2, b3);
        }

        // ---- exp (no max needed: |s| << 1), pack P, accumulate l ----
        unsigned pu[4][4];
        #pragma unroll
        for (int t = 0; t < 8; t++) {
            float e0 = __expf(s[t][0]);
            float e1 = __expf(s[t][1]);
            float e2 = __expf(s[t][2]);
            float e3 = __expf(s[t][3]);
            l0 += e0 + e1;
            l1 += e2 + e3;
            int lo = (t & 1) ? 2 : 0;
            pu[t >> 1][lo + 0] = pack_h2(e0, e1);
            pu[t >> 1][lo + 1] = pack_h2(e2, e3);
        }

        // ---- O += P V  (16 x 32 per warp), V via ldmatrix.trans ----
        #pragma unroll
        for (int jc = 0; jc < 4; jc++) {
            uint32_t a0 = vbase +
                (uint32_t)(((jc * 16 + (lane & 15)) * PITCH + (lane >> 4) * 8) * 2);
            unsigned r0, r1, r2, r3;
            LDMX4T(r0, r1, r2, r3, a0);
            MMA16816(o[0], pu[jc], r0, r1);
            MMA16816(o[1], pu[jc], r2, r3);
            LDMX4T(r0, r1, r2, r3, a0 + 32);   // +16 halves
            MMA16816(o[2], pu[jc], r0, r1);
            MMA16816(o[3], pu[jc], r2, r3);
        }
        __syncthreads();     // reads of stage st done before kb+2 overwrites it
    }

    // ---- finalize: row-sum reduce l across quad, divide, write ----
    l0 += __shfl_xor_sync(0xffffffffu, l0, 1);
    l0 += __shfl_xor_sync(0xffffffffu, l0, 2);
    l1 += __shfl_xor_sync(0xffffffffu, l1, 1);
    l1 += __shfl_xor_sync(0xffffffffu, l1, 2);
    float inv0 = 1.0f / l0, inv1 = 1.0f / l1;

    int b = bh >> 2, h = bh & 3;
    int row0 = qt * 128 + rb + g;
    float* dst0 = g_Of + (b * N_ + row0) * 128 + h * 32;
    float* dst1 = dst0 + 8 * 128;
    #pragma unroll
    for (int t = 0; t < 4; t++) {
        int d = t * 8 + q2;
        *(float2*)&dst0[d] = make_float2(o[t][0] * inv0, o[t][1] * inv0);
        *(float2*)&dst1[d] = make_float2(o[t][2] * inv1, o[t][3] * inv1);
    }
}

// =====================================================================
// Kernel 5: output projection  (Of[16384,128] @ Wout[128,128]) + bias
// =====================================================================
__global__ __launch_bounds__(256) void gemm_out_kernel(
    const float* __restrict__ W, const float* __restrict__ bias,
    float* __restrict__ out)
{
    __shared__ float As[16][64];
    __shared__ float Bs[16][64];
    const int tid = threadIdx.x;
    const int m0 = blockIdx.y * 64;
    const int n0 = blockIdx.x * 64;
    const int tm = (tid >> 4) * 4;
    const int tn = (tid & 15) * 4;

    float acc[4][4];
    #pragma unroll
    for (int i = 0; i < 4; i++)
        #pragma unroll
        for (int j = 0; j < 4; j++) acc[i][j] = 0.f;

    for (int kb = 0; kb < 128; kb += 16) {
        {
            int r = tid >> 2, c = (tid & 3) * 4;
            float4 v = *(const float4*)&g_Of[(m0 + r) * 128 + kb + c];
            As[c + 0][r] = v.x; As[c + 1][r] = v.y;
            As[c + 2][r] = v.z; As[c + 3][r] = v.w;
            int rk = tid >> 4, cn = (tid & 15) * 4;
            *(float4*)&Bs[rk][cn] = *(const float4*)&W[(kb + rk) * 128 + n0 + cn];
        }
        __syncthreads();
        #pragma unroll
        for (int kk = 0; kk < 16; kk++) {
            float a[4], b[4];
            #pragma unroll
            for (int i = 0; i < 4; i++) a[i] = As[kk][tm + i];
            #pragma unroll
            for (int j = 0; j < 4; j++) b[j] = Bs[kk][tn + j];
            #pragma unroll
            for (int i = 0; i < 4; i++)
                #pragma unroll
                for (int j = 0; j < 4; j++) acc[i][j] += a[i] * b[j];
        }
        __syncthreads();
    }

    float4 bv = *(const float4*)&bias[n0 + tn];
    #pragma unroll
    for (int i = 0; i < 4; i++) {
        int m = m0 + tm + i;
        *(float4*)&out[m * 128 + n0 + tn] =
            make_float4(acc[i][0] + bv.x, acc[i][1] + bv.y,
                        acc[i][2] + bv.z, acc[i][3] + bv.w);
    }
}

// =====================================================================
extern "C" void kernel_launch(void* const* d_in, const int* in_sizes, int n_in,
                              void* d_out, int out_size)
{
    const float* x     = (const float*)d_in[0];   // [4,4096,128]
    const float* Wqkv  = (const float*)d_in[1];   // [128,384]
    const float* Wout  = (const float*)d_in[2];   // [128,128]
    const float* bout  = (const float*)d_in[3];   // [128]
    float* out = (float*)d_out;                   // [4,4096,128]

    gemm_qkv_kernel<<<dim3(6, 256), 256>>>(x, Wqkv);
    colnorm_kernel<<<32, 256>>>();
    normalize_kernel<<<QK_ELEMS / 256, 256>>>();
    flash_kernel<<<dim3(32, 16), 256>>>();
    gemm_out_kernel<<<dim3(2, 256), 256>>>(Wout, bout, out);
}

// round 5
// speedup vs baseline: 1.9427x; 1.4013x over previous
#include <cuda_runtime.h>
#include <cuda_fp16.h>
#include <cstdint>

// Problem constants
#define B_   4
#define N_   4096
#define C_   128
#define H_   4
#define D_   32
#define BH_  (B_*H_)           // 16
#define QK_ELEMS (BH_*N_*D_)   // 2,097,152

// ---------------- static scratch (no allocs allowed) ----------------
__device__ __half g_Xh[B_*N_*C_];        // x in fp16
__device__ __half g_Wqkvh[C_*3*C_];      // W_qkv in fp16
__device__ __half g_Wouth[C_*C_];        // W_out in fp16
__device__ float  g_Qf[QK_ELEMS];
__device__ float  g_Kf[QK_ELEMS];
__device__ __half g_Qh[QK_ELEMS];
__device__ __half g_Kh[QK_ELEMS];
__device__ __half g_Vh[QK_ELEMS];
__device__ __half g_Oh[B_*N_*C_];        // attention output fp16 [b][n][h*32+d]
__device__ float  g_qinv[BH_*D_];        // 10*log2(e) / norm
__device__ float  g_kinv[BH_*D_];        // 1 / norm

// ---------------- PTX helpers ----------------
#define MMA16816(d, a, b0, b1)                                                  \
    asm volatile("mma.sync.aligned.m16n8k16.row.col.f32.f16.f16.f32 "          \
        "{%0,%1,%2,%3}, {%4,%5,%6,%7}, {%8,%9}, {%0,%1,%2,%3};\n"              \
        : "+f"(d[0]), "+f"(d[1]), "+f"(d[2]), "+f"(d[3])                        \
        : "r"(a[0]), "r"(a[1]), "r"(a[2]), "r"(a[3]), "r"(b0), "r"(b1))

#define LDMX4(r0,r1,r2,r3,addr)                                                 \
    asm volatile("ldmatrix.sync.aligned.m8n8.x4.shared.b16 {%0,%1,%2,%3}, [%4];\n" \
        : "=r"(r0), "=r"(r1), "=r"(r2), "=r"(r3) : "r"(addr))

#define LDMX4T(r0,r1,r2,r3,addr)                                                \
    asm volatile("ldmatrix.sync.aligned.m8n8.x4.trans.shared.b16 {%0,%1,%2,%3}, [%4];\n" \
        : "=r"(r0), "=r"(r1), "=r"(r2), "=r"(r3) : "r"(addr))

__device__ __forceinline__ void cp16(uint32_t dst, const void* src) {
    asm volatile("cp.async.cg.shared.global [%0], [%1], 16;\n" :: "r"(dst), "l"(src));
}
#define CP_COMMIT() asm volatile("cp.async.commit_group;\n" ::: "memory")
#define CP_WAIT0()  asm volatile("cp.async.wait_group 0;\n" ::: "memory")

__device__ __forceinline__ float ex2f(float x) {
    float r; asm("ex2.approx.f32 %0, %1;" : "=f"(r) : "f"(x)); return r;
}
__device__ __forceinline__ unsigned pack_h2(float x, float y) {
    __half2 h = __float22half2_rn(make_float2(x, y));
    return *reinterpret_cast<unsigned*>(&h);
}

// =====================================================================
// Convert kernels (fp32 -> fp16)
// =====================================================================
__global__ __launch_bounds__(256) void cvt_x_kernel(const float4* __restrict__ src)
{
    int i = blockIdx.x * 256 + threadIdx.x;   // 524288 float4 chunks
    float4 v = src[i];
    __half2* dst = (__half2*)g_Xh;
    dst[2*i + 0] = __float22half2_rn(make_float2(v.x, v.y));
    dst[2*i + 1] = __float22half2_rn(make_float2(v.z, v.w));
}

__global__ __launch_bounds__(256) void cvt_w_kernel(
    const float4* __restrict__ wqkv, const float4* __restrict__ wout)
{
    int i = blockIdx.x * 256 + threadIdx.x;   // 16384 chunks total
    if (i < 12288) {
        float4 v = wqkv[i];
        __half2* dst = (__half2*)g_Wqkvh;
        dst[2*i + 0] = __float22half2_rn(make_float2(v.x, v.y));
        dst[2*i + 1] = __float22half2_rn(make_float2(v.z, v.w));
    } else {
        int j = i - 12288;
        float4 v = wout[j];
        __half2* dst = (__half2*)g_Wouth;
        dst[2*j + 0] = __float22half2_rn(make_float2(v.x, v.y));
        dst[2*j + 1] = __float22half2_rn(make_float2(v.z, v.w));
    }
}

// =====================================================================
// Kernel 1: QKV GEMM fp16 tensor-core  (Xh[16384,128] @ Wh[128,384]),
// fp32 acc, routes q->g_Qf, k->g_Kf (fp32), v->g_Vh (fp16), [bh][n][d].
// grid (6 n-chunks of 64, 128 m-tiles of 128), 256 threads (8 warps).
// =====================================================================
#define GP 72   // smem pitch in halves

__global__ __launch_bounds__(256) void gemm_qkv_h()
{
    __shared__ __align__(16) __half As[128][GP];
    __shared__ __align__(16) __half Bs[64][GP];
    const int nc  = blockIdx.x;       // 0..5
    const int mt  = blockIdx.y;       // 0..127
    const int tid = threadIdx.x;
    const int lane = tid & 31;
    const int warp = tid >> 5;
    const int g    = lane >> 2;
    const int q2   = (lane & 3) * 2;

    const uint32_t as_base = (uint32_t)__cvta_generic_to_shared(&As[0][0]);
    const uint32_t bs_base = (uint32_t)__cvta_generic_to_shared(&Bs[0][0]);
    const __half* Ap = g_Xh + mt * 128 * 128;
    const __half* Bp = g_Wqkvh + nc * 64;

    float acc[8][4];
    #pragma unroll
    for (int t = 0; t < 8; t++)
        #pragma unroll
        for (int r = 0; r < 4; r++) acc[t][r] = 0.f;

    #pragma unroll
    for (int p = 0; p < 2; p++) {
        if (p) __syncthreads();
        #pragma unroll
        for (int j = 0; j < 4; j++) {        // A: 1024 chunks of 16B
            int i = tid + j * 256;
            int row = i >> 3, c8 = (i & 7) * 8;
            cp16(as_base + (uint32_t)((row * GP + c8) * 2),
                 Ap + row * 128 + p * 64 + c8);
        }
        #pragma unroll
        for (int j = 0; j < 2; j++) {        // B: 512 chunks
            int i = tid + j * 256;
            int row = i >> 3, c8 = (i & 7) * 8;
            cp16(bs_base + (uint32_t)((row * GP + c8) * 2),
                 Bp + (p * 64 + row) * 384 + c8);
        }
        CP_COMMIT(); CP_WAIT0();
        __syncthreads();

        #pragma unroll
        for (int kc = 0; kc < 4; kc++) {
            unsigned a[4];
            LDMX4(a[0], a[1], a[2], a[3], as_base +
                (uint32_t)(((warp * 16 + (lane & 15)) * GP + kc * 16 + (lane >> 4) * 8) * 2));
            #pragma unroll
            for (int t = 0; t < 4; t++) {
                unsigned b0, b1, b2, b3;
                LDMX4T(b0, b1, b2, b3, bs_base +
                    (uint32_t)(((kc * 16 + (lane & 15)) * GP + t * 16 + (lane >> 4) * 8) * 2));
                MMA16816(acc[2 * t],     a, b0, b1);
                MMA16816(acc[2 * t + 1], a, b2, b3);
            }
        }
    }

    // epilogue
    #pragma unroll
    for (int t = 0; t < 8; t++) {
        int e  = nc * 64 + t * 8 + q2;
        int ec = e & 127;
        int h  = ec >> 5, d = ec & 31;
        #pragma unroll
        for (int half_ = 0; half_ < 2; half_++) {
            int m = mt * 128 + warp * 16 + g + half_ * 8;
            int b = m >> 12, n = m & 4095;
            int idx = ((b * 4 + h) * 4096 + n) * 32 + d;
            float v0 = acc[t][half_ * 2], v1 = acc[t][half_ * 2 + 1];
            if (nc < 2)      *(float2*)&g_Qf[idx] = make_float2(v0, v1);
            else if (nc < 4) *(float2*)&g_Kf[idx] = make_float2(v0, v1);
            else *(__half2*)&g_Vh[idx] = __float22half2_rn(make_float2(v0, v1));
        }
    }
}

// =====================================================================
// Kernel 2: column sum-of-squares over N per (bh,d), for q and k.
// =====================================================================
__global__ __launch_bounds__(256) void colnorm_kernel()
{
    const int bh = blockIdx.x & 15;
    const int which = blockIdx.x >> 4;     // 0 = q, 1 = k
    const float* src = (which ? g_Kf : g_Qf) + bh * N_ * D_;
    const int d = threadIdx.x & 31;
    const int grp = threadIdx.x >> 5;      // 0..7

    float s = 0.f;
    for (int n = grp; n < N_; n += 8) {
        float v = src[n * 32 + d];
        s += v * v;
    }
    __shared__ float red[256];
    red[threadIdx.x] = s;
    __syncthreads();
    if (threadIdx.x < 32) {
        float tot = 0.f;
        #pragma unroll
        for (int g = 0; g < 8; g++) tot += red[g * 32 + d];
        float nrm = fmaxf(sqrtf(tot), 1e-12f);
        if (which) g_kinv[bh * 32 + d] = 1.0f / nrm;
        else       g_qinv[bh * 32 + d] = 14.4269504088896f / nrm; // 10*log2(e), exp2 domain
    }
}

// =====================================================================
// Kernel 3: normalize + convert to fp16
// =====================================================================
__global__ __launch_bounds__(256) void normalize_kernel()
{
    int i = blockIdx.x * 256 + threadIdx.x;   // 0 .. QK_ELEMS-1
    int col = ((i >> 17) << 5) | (i & 31);    // bh*32 + d
    g_Qh[i] = __float2half(g_Qf[i] * g_qinv[col]);
    g_Kh[i] = __float2half(g_Kf[i] * g_kinv[col]);
}

// =====================================================================
// Kernel 4: flash attention, fp16 mma, fp32 accum, exp2-domain softmax,
// row-sum l via ones-MMA, single __syncthreads per iteration.
// grid (32 q-tiles of 128, 16 bh), 256 threads (8 warps x m16).
// =====================================================================
#define PITCH     40                    // halves per smem row
#define KV_BYTES  (64 * PITCH * 2)      // bytes per K or V stage

__global__ __launch_bounds__(256) void flash_kernel()
{
    const int qt   = blockIdx.x;      // 0..31
    const int bh   = blockIdx.y;      // 0..15
    const int tid  = threadIdx.x;
    const int lane = tid & 31;
    const int warp = tid >> 5;        // 0..7
    const int g    = lane >> 2;       // 0..7
    const int q2   = (lane & 3) * 2;  // 0,2,4,6

    __shared__ __align__(16) __half Qs[128][PITCH];
    __shared__ __align__(16) __half Ks[2][64][PITCH];
    __shared__ __align__(16) __half Vs[2][64][PITCH];

    const __half* Qg = g_Qh + (bh * N_ + qt * 128) * 32;
    const __half* Kg = g_Kh + bh * N_ * 32;
    const __half* Vg = g_Vh + bh * N_ * 32;

    const uint32_t qs_base = (uint32_t)__cvta_generic_to_shared(&Qs[0][0]);
    const uint32_t ks_base = (uint32_t)__cvta_generic_to_shared(&Ks[0][0][0]);
    const uint32_t vs_base = (uint32_t)__cvta_generic_to_shared(&Vs[0][0][0]);

    const int crow = tid >> 2;
    const int ccol = (tid & 3) * 8;
    const uint32_t cdst = (uint32_t)(crow * (PITCH * 2) + ccol * 2);
    const int     csrc  = crow * 32 + ccol;

    // prefetch tile 0
    cp16(ks_base + cdst, Kg + csrc);
    cp16(vs_base + cdst, Vg + csrc);
    CP_COMMIT();

    // stage Q while tile 0 streams
    {
        const int4* src = (const int4*)Qg;
        #pragma unroll
        for (int i = tid; i < 512; i += 256) {
            int4 v = src[i];
            *(int4*)&Qs[i >> 2][(i & 3) * 8] = v;
        }
    }
    __syncthreads();

    // Q A-fragments for the whole loop
    unsigned qa[2][4];
    const int rb = warp * 16;
    #pragma unroll
    for (int kc = 0; kc < 2; kc++) {
        uint32_t addr = qs_base +
            (uint32_t)(((rb + (lane & 15)) * PITCH + kc * 16 + (lane >> 4) * 8) * 2);
        LDMX4(qa[kc][0], qa[kc][1], qa[kc][2], qa[kc][3], addr);
    }

    float o[4][4];
    #pragma unroll
    for (int t = 0; t < 4; t++)
        #pragma unroll
        for (int r = 0; r < 4; r++) o[t][r] = 0.f;
    float lacc[4] = {0.f, 0.f, 0.f, 0.f};
    const unsigned ONES = 0x3C003C00u;    // (1.0h, 1.0h)

    for (int kb = 0; kb < 64; kb++) {
        const int st = kb & 1;
        CP_WAIT0();            // stage kb arrived (per-thread)
        __syncthreads();       // block-wide: stage kb visible; iter kb-1 compute done

        if (kb + 1 < 64) {     // prefetch overlaps this iteration's compute
            uint32_t off = (uint32_t)((st ^ 1) * KV_BYTES) + cdst;
            int s2 = (kb + 1) * 64 * 32 + csrc;
            cp16(ks_base + off, Kg + s2);
            cp16(vs_base + off, Vg + s2);
            CP_COMMIT();
        }

        const uint32_t kbase = ks_base + st * KV_BYTES;
        const uint32_t vbase = vs_base + st * KV_BYTES;

        // ---- S = Q K^T  (16 x 64 per warp), exp2 domain ----
        float s[8][4];
        #pragma unroll
        for (int t = 0; t < 8; t++) {
            unsigned b0, b1, b2, b3;
            uint32_t addr = kbase +
                (uint32_t)(((t * 8 + (lane & 7)) * PITCH + (lane >> 3) * 8) * 2);
            LDMX4(b0, b1, b2, b3, addr);
            s[t][0] = s[t][1] = s[t][2] = s[t][3] = 0.f;
            MMA16816(s[t], qa[0], b0, b1);
            MMA16816(s[t], qa[1], b2, b3);
        }

        // ---- per jc-chunk: exp2 + pack + l-MMA + PV MMAs (pipes overlap) ----
        #pragma unroll
        for (int jc = 0; jc < 4; jc++) {
            float e00 = ex2f(s[2*jc][0]),   e01 = ex2f(s[2*jc][1]);
            float e02 = ex2f(s[2*jc][2]),   e03 = ex2f(s[2*jc][3]);
            float e10 = ex2f(s[2*jc+1][0]), e11 = ex2f(s[2*jc+1][1]);
            float e12 = ex2f(s[2*jc+1][2]), e13 = ex2f(s[2*jc+1][3]);
            unsigned pu[4];
            pu[0] = pack_h2(e00, e01);
            pu[1] = pack_h2(e02, e03);
            pu[2] = pack_h2(e10, e11);
            pu[3] = pack_h2(e12, e13);

            MMA16816(lacc, pu, ONES, ONES);   // row sums -> persistent fp32 acc

            uint32_t a0 = vbase +
                (uint32_t)(((jc * 16 + (lane & 15)) * PITCH + (lane >> 4) * 8) * 2);
            unsigned r0, r1, r2, r3;
            LDMX4T(r0, r1, r2, r3, a0);
            MMA16816(o[0], pu, r0, r1);
            MMA16816(o[1], pu, r2, r3);
            LDMX4T(r0, r1, r2, r3, a0 + 32);
            MMA16816(o[2], pu, r0, r1);
            MMA16816(o[3], pu, r2, r3);
        }
    }

    // ---- finalize: l is broadcast across accumulator columns ----
    float inv0 = 1.0f / lacc[0];
    float inv1 = 1.0f / lacc[2];

    int b = bh >> 2, h = bh & 3;
    int row0 = qt * 128 + rb + g;
    __half* dst0 = g_Oh + (b * N_ + row0) * 128 + h * 32;
    __half* dst1 = dst0 + 8 * 128;
    #pragma unroll
    for (int t = 0; t < 4; t++) {
        int d = t * 8 + q2;
        *(__half2*)&dst0[d] = __float22half2_rn(make_float2(o[t][0] * inv0, o[t][1] * inv0));
        *(__half2*)&dst1[d] = __float22half2_rn(make_float2(o[t][2] * inv1, o[t][3] * inv1));
    }
}

// =====================================================================
// Kernel 5: output projection fp16 tensor-core (Oh[16384,128] @ Wo[128,128])
// + bias, fp32 out. grid (2 n-chunks, 128 m-tiles), 256 threads.
// =====================================================================
__global__ __launch_bounds__(256) void gemm_out_h(
    const float* __restrict__ bias, float* __restrict__ out)
{
    __shared__ __align__(16) __half As[128][GP];
    __shared__ __align__(16) __half Bs[64][GP];
    const int nc  = blockIdx.x;       // 0..1
    const int mt  = blockIdx.y;       // 0..127
    const int tid = threadIdx.x;
    const int lane = tid & 31;
    const int warp = tid >> 5;
    const int g    = lane >> 2;
    const int q2   = (lane & 3) * 2;

    const uint32_t as_base = (uint32_t)__cvta_generic_to_shared(&As[0][0]);
    const uint32_t bs_base = (uint32_t)__cvta_generic_to_shared(&Bs[0][0]);
    const __half* Ap = g_Oh + mt * 128 * 128;
    const __half* Bp = g_Wouth + nc * 64;

    float acc[8][4];
    #pragma unroll
    for (int t = 0; t < 8; t++)
        #pragma unroll
        for (int r = 0; r < 4; r++) acc[t][r] = 0.f;

    #pragma unroll
    for (int p = 0; p < 2; p++) {
        if (p) __syncthreads();
        #pragma unroll
        for (int j = 0; j < 4; j++) {
            int i = tid + j * 256;
            int row = i >> 3, c8 = (i & 7) * 8;
            cp16(as_base + (uint32_t)((row * GP + c8) * 2),
                 Ap + row * 128 + p * 64 + c8);
        }
        #pragma unroll
        for (int j = 0; j < 2; j++) {
            int i = tid + j * 256;
            int row = i >> 3, c8 = (i & 7) * 8;
            cp16(bs_base + (uint32_t)((row * GP + c8) * 2),
                 Bp + (p * 64 + row) * 128 + c8);
        }
        CP_COMMIT(); CP_WAIT0();
        __syncthreads();

        #pragma unroll
        for (int kc = 0; kc < 4; kc++) {
            unsigned a[4];
            LDMX4(a[0], a[1], a[2], a[3], as_base +
                (uint32_t)(((warp * 16 + (lane & 15)) * GP + kc * 16 + (lane >> 4) * 8) * 2));
            #pragma unroll
            for (int t = 0; t < 4; t++) {
                unsigned b0, b1, b2, b3;
                LDMX4T(b0, b1, b2, b3, bs_base +
                    (uint32_t)(((kc * 16 + (lane & 15)) * GP + t * 16 + (lane >> 4) * 8) * 2));
                MMA16816(acc[2 * t],     a, b0, b1);
                MMA16816(acc[2 * t + 1], a, b2, b3);
            }
        }
    }

    #pragma unroll
    for (int t = 0; t < 8; t++) {
        int e = nc * 64 + t * 8 + q2;
        float2 bv = *(const float2*)&bias[e];
        #pragma unroll
        for (int half_ = 0; half_ < 2; half_++) {
            int m = mt * 128 + warp * 16 + g + half_ * 8;
            *(float2*)&out[m * 128 + e] =
                make_float2(acc[t][half_ * 2] + bv.x, acc[t][half_ * 2 + 1] + bv.y);
        }
    }
}

// =====================================================================
extern "C" void kernel_launch(void* const* d_in, const int* in_sizes, int n_in,
                              void* d_out, int out_size)
{
    const float* x     = (const float*)d_in[0];   // [4,4096,128]
    const float* Wqkv  = (const float*)d_in[1];   // [128,384]
    const float* Wout  = (const float*)d_in[2];   // [128,128]
    const float* bout  = (const float*)d_in[3];   // [128]
    float* out = (float*)d_out;                   // [4,4096,128]

    cvt_x_kernel<<<2048, 256>>>((const float4*)x);
    cvt_w_kernel<<<64, 256>>>((const float4*)Wqkv, (const float4*)Wout);
    gemm_qkv_h<<<dim3(6, 128), 256>>>();
    colnorm_kernel<<<32, 256>>>();
    normalize_kernel<<<QK_ELEMS / 256, 256>>>();
    flash_kernel<<<dim3(32, 16), 256>>>();
    gemm_out_h<<<dim3(2, 128), 256>>>(bout, out);
}

// round 6
// speedup vs baseline: 2.4002x; 1.2355x over previous
#include <cuda_runtime.h>
#include <cuda_fp16.h>
#include <cstdint>

// Problem constants
#define B_   4
#define N_   4096
#define C_   128
#define H_   4
#define D_   32
#define BH_  (B_*H_)           // 16
#define QK_ELEMS (BH_*N_*D_)   // 2,097,152

// ---------------- static scratch (no allocs allowed) ----------------
__device__ __half g_Xh[B_*N_*C_];        // x in fp16
__device__ __half g_Wqkvh[C_*3*C_];      // W_qkv in fp16
__device__ __half g_Wouth[C_*C_];        // W_out in fp16
__device__ __half g_Qh[QK_ELEMS];        // raw q (unnormalized) fp16
__device__ __half g_Kh[QK_ELEMS];        // raw k fp16 (final: scale folded into Q)
__device__ __half g_Vh[QK_ELEMS];
__device__ __half g_Oh[B_*N_*C_];        // attention output fp16 [b][n][h*32+d]
__device__ float  g_part[2][8][512];     // column sumsq partials [q/k][chunk][bh*32+d]
__device__ float  g_scale[512];          // 10*log2e / (qnorm*knorm) per (bh,d)

// ---------------- PTX helpers ----------------
#define MMA16816(d, a, b0, b1)                                                  \
    asm volatile("mma.sync.aligned.m16n8k16.row.col.f32.f16.f16.f32 "          \
        "{%0,%1,%2,%3}, {%4,%5,%6,%7}, {%8,%9}, {%0,%1,%2,%3};\n"              \
        : "+f"(d[0]), "+f"(d[1]), "+f"(d[2]), "+f"(d[3])                        \
        : "r"(a[0]), "r"(a[1]), "r"(a[2]), "r"(a[3]), "r"(b0), "r"(b1))

#define LDMX4(r0,r1,r2,r3,addr)                                                 \
    asm volatile("ldmatrix.sync.aligned.m8n8.x4.shared.b16 {%0,%1,%2,%3}, [%4];\n" \
        : "=r"(r0), "=r"(r1), "=r"(r2), "=r"(r3) : "r"(addr))

#define LDMX4T(r0,r1,r2,r3,addr)                                                \
    asm volatile("ldmatrix.sync.aligned.m8n8.x4.trans.shared.b16 {%0,%1,%2,%3}, [%4];\n" \
        : "=r"(r0), "=r"(r1), "=r"(r2), "=r"(r3) : "r"(addr))

__device__ __forceinline__ void cp16(uint32_t dst, const void* src) {
    asm volatile("cp.async.cg.shared.global [%0], [%1], 16;\n" :: "r"(dst), "l"(src));
}
#define CP_COMMIT() asm volatile("cp.async.commit_group;\n" ::: "memory")
#define CP_WAIT0()  asm volatile("cp.async.wait_group 0;\n" ::: "memory")

__device__ __forceinline__ unsigned pack_h2(float x, float y) {
    __half2 h = __float22half2_rn(make_float2(x, y));
    return *reinterpret_cast<unsigned*>(&h);
}
__device__ __forceinline__ unsigned ex2h2(unsigned x) {
    unsigned r; asm("ex2.approx.f16x2 %0, %1;" : "=r"(r) : "r"(x)); return r;
}

// =====================================================================
// Convert kernel (fp32 -> fp16): x, W_qkv, W_out in one launch
// =====================================================================
__global__ __launch_bounds__(256) void cvt_all_kernel(
    const float4* __restrict__ x, const float4* __restrict__ wqkv,
    const float4* __restrict__ wout)
{
    int bid = blockIdx.x;
    if (bid < 2048) {
        int i = bid * 256 + threadIdx.x;       // 524288 chunks
        float4 v = x[i];
        __half2* dst = (__half2*)g_Xh;
        dst[2*i + 0] = __float22half2_rn(make_float2(v.x, v.y));
        dst[2*i + 1] = __float22half2_rn(make_float2(v.z, v.w));
    } else {
        int i = (bid - 2048) * 256 + threadIdx.x;  // 16384 chunks
        if (i < 12288) {
            float4 v = wqkv[i];
            __half2* dst = (__half2*)g_Wqkvh;
            dst[2*i + 0] = __float22half2_rn(make_float2(v.x, v.y));
            dst[2*i + 1] = __float22half2_rn(make_float2(v.z, v.w));
        } else {
            int j = i - 12288;
            float4 v = wout[j];
            __half2* dst = (__half2*)g_Wouth;
            dst[2*j + 0] = __float22half2_rn(make_float2(v.x, v.y));
            dst[2*j + 1] = __float22half2_rn(make_float2(v.z, v.w));
        }
    }
}

// =====================================================================
// Kernel 1: QKV GEMM fp16 tensor-core (Xh[16384,128] @ Wh[128,384]),
// fp32 acc, writes q/k/v all fp16 in [bh][n][d] layout.
// =====================================================================
#define GP 72   // smem pitch in halves

__global__ __launch_bounds__(256) void gemm_qkv_h()
{
    __shared__ __align__(16) __half As[128][GP];
    __shared__ __align__(16) __half Bs[64][GP];
    const int nc  = blockIdx.x;       // 0..5
    const int mt  = blockIdx.y;       // 0..127
    const int tid = threadIdx.x;
    const int lane = tid & 31;
    const int warp = tid >> 5;
    const int g    = lane >> 2;
    const int q2   = (lane & 3) * 2;

    const uint32_t as_base = (uint32_t)__cvta_generic_to_shared(&As[0][0]);
    const uint32_t bs_base = (uint32_t)__cvta_generic_to_shared(&Bs[0][0]);
    const __half* Ap = g_Xh + mt * 128 * 128;
    const __half* Bp = g_Wqkvh + nc * 64;

    float acc[8][4];
    #pragma unroll
    for (int t = 0; t < 8; t++)
        #pragma unroll
        for (int r = 0; r < 4; r++) acc[t][r] = 0.f;

    #pragma unroll
    for (int p = 0; p < 2; p++) {
        if (p) __syncthreads();
        #pragma unroll
        for (int j = 0; j < 4; j++) {        // A: 1024 chunks of 16B
            int i = tid + j * 256;
            int row = i >> 3, c8 = (i & 7) * 8;
            cp16(as_base + (uint32_t)((row * GP + c8) * 2),
                 Ap + row * 128 + p * 64 + c8);
        }
        #pragma unroll
        for (int j = 0; j < 2; j++) {        // B: 512 chunks
            int i = tid + j * 256;
            int row = i >> 3, c8 = (i & 7) * 8;
            cp16(bs_base + (uint32_t)((row * GP + c8) * 2),
                 Bp + (p * 64 + row) * 384 + c8);
        }
        CP_COMMIT(); CP_WAIT0();
        __syncthreads();

        #pragma unroll
        for (int kc = 0; kc < 4; kc++) {
            unsigned a[4];
            LDMX4(a[0], a[1], a[2], a[3], as_base +
                (uint32_t)(((warp * 16 + (lane & 15)) * GP + kc * 16 + (lane >> 4) * 8) * 2));
            #pragma unroll
            for (int t = 0; t < 4; t++) {
                unsigned b0, b1, b2, b3;
                LDMX4T(b0, b1, b2, b3, bs_base +
                    (uint32_t)(((kc * 16 + (lane & 15)) * GP + t * 16 + (lane >> 4) * 8) * 2));
                MMA16816(acc[2 * t],     a, b0, b1);
                MMA16816(acc[2 * t + 1], a, b2, b3);
            }
        }
    }

    // epilogue: all fp16
    #pragma unroll
    for (int t = 0; t < 8; t++) {
        int e  = nc * 64 + t * 8 + q2;
        int ec = e & 127;
        int h  = ec >> 5, d = ec & 31;
        #pragma unroll
        for (int half_ = 0; half_ < 2; half_++) {
            int m = mt * 128 + warp * 16 + g + half_ * 8;
            int b = m >> 12, n = m & 4095;
            int idx = ((b * 4 + h) * 4096 + n) * 32 + d;
            __half2 hv = __float22half2_rn(
                make_float2(acc[t][half_ * 2], acc[t][half_ * 2 + 1]));
            if (nc < 2)      *(__half2*)&g_Qh[idx] = hv;
            else if (nc < 4) *(__half2*)&g_Kh[idx] = hv;
            else             *(__half2*)&g_Vh[idx] = hv;
        }
    }
}

// =====================================================================
// Kernel 2a: column sum-of-squares partials (fp16 src, fp32 acc).
// grid 256 = 16 bh x {q,k} x 8 chunks of 512 rows. Deterministic.
// =====================================================================
__global__ __launch_bounds__(256) void colnorm_partial()
{
    const int bx = blockIdx.x;
    const int bh = bx & 15;
    const int r  = bx >> 4;
    const int which = r & 1;          // 0 = q, 1 = k
    const int chunk = r >> 1;         // 0..7
    const __half* src = (which ? g_Kh : g_Qh) + (bh * N_ + chunk * 512) * 32;
    const int d = threadIdx.x & 31;
    const int grp = threadIdx.x >> 5;

    float s = 0.f;
    for (int n = grp; n < 512; n += 8) {
        float v = __half2float(src[n * 32 + d]);
        s = fmaf(v, v, s);
    }
    __shared__ float red[256];
    red[threadIdx.x] = s;
    __syncthreads();
    if (threadIdx.x < 32) {
        float tot = 0.f;
        #pragma unroll
        for (int g = 0; g < 8; g++) tot += red[g * 32 + d];
        g_part[which][chunk][bh * 32 + d] = tot;
    }
}

// Kernel 2b: finalize scale = 10*log2(e) / (qnorm * knorm)
__global__ __launch_bounds__(512) void finalize_scale()
{
    int col = threadIdx.x;   // 0..511
    float qs = 0.f, ks = 0.f;
    #pragma unroll
    for (int c = 0; c < 8; c++) {
        qs += g_part[0][c][col];
        ks += g_part[1][c][col];
    }
    float qn = fmaxf(sqrtf(qs), 1e-12f);
    float kn = fmaxf(sqrtf(ks), 1e-12f);
    g_scale[col] = 14.4269504088896f / (qn * kn);
}

// =====================================================================
// Kernel 3: flash attention. Q scale applied at staging; exp via
// ex2.approx.f16x2; row-sum l via ones-MMA; 1 barrier/iter.
// grid (32 q-tiles of 128, 16 bh), 256 threads (8 warps x m16).
// =====================================================================
#define PITCH     40                    // halves per smem row
#define KV_BYTES  (64 * PITCH * 2)      // bytes per K or V stage

__global__ __launch_bounds__(256) void flash_kernel()
{
    const int qt   = blockIdx.x;      // 0..31
    const int bh   = blockIdx.y;      // 0..15
    const int tid  = threadIdx.x;
    const int lane = tid & 31;
    const int warp = tid >> 5;        // 0..7
    const int g    = lane >> 2;       // 0..7

    __shared__ __align__(16) __half Qs[128][PITCH];
    __shared__ __align__(16) __half Ks[2][64][PITCH];
    __shared__ __align__(16) __half Vs[2][64][PITCH];

    const __half* Qg = g_Qh + (bh * N_ + qt * 128) * 32;
    const __half* Kg = g_Kh + bh * N_ * 32;
    const __half* Vg = g_Vh + bh * N_ * 32;

    const uint32_t qs_base = (uint32_t)__cvta_generic_to_shared(&Qs[0][0]);
    const uint32_t ks_base = (uint32_t)__cvta_generic_to_shared(&Ks[0][0][0]);
    const uint32_t vs_base = (uint32_t)__cvta_generic_to_shared(&Vs[0][0][0]);

    const int crow = tid >> 2;
    const int ccol = (tid & 3) * 8;
    const uint32_t cdst = (uint32_t)(crow * (PITCH * 2) + ccol * 2);
    const int     csrc  = crow * 32 + ccol;

    // prefetch KV tile 0
    cp16(ks_base + cdst, Kg + csrc);
    cp16(vs_base + cdst, Vg + csrc);
    CP_COMMIT();

    // stage Q (raw fp16 * fp32 scale -> fp16) while tile 0 streams
    {
        const int d0 = (tid & 3) * 8;       // constant across both chunks
        float sc[8];
        #pragma unroll
        for (int j = 0; j < 8; j++) sc[j] = g_scale[bh * 32 + d0 + j];
        const int4* src = (const int4*)Qg;
        #pragma unroll
        for (int i = tid; i < 512; i += 256) {
            int4 v = src[i];
            __half2* hp = (__half2*)&v;
            #pragma unroll
            for (int j = 0; j < 4; j++) {
                float2 f = __half22float2(hp[j]);
                f.x *= sc[2 * j]; f.y *= sc[2 * j + 1];
                hp[j] = __float22half2_rn(f);
            }
            *(int4*)&Qs[i >> 2][(i & 3) * 8] = v;
        }
    }
    __syncthreads();

    // Q A-fragments for the whole loop
    unsigned qa[2][4];
    const int rb = warp * 16;
    #pragma unroll
    for (int kc = 0; kc < 2; kc++) {
        uint32_t addr = qs_base +
            (uint32_t)(((rb + (lane & 15)) * PITCH + kc * 16 + (lane >> 4) * 8) * 2);
        LDMX4(qa[kc][0], qa[kc][1], qa[kc][2], qa[kc][3], addr);
    }

    float o[4][4];
    #pragma unroll
    for (int t = 0; t < 4; t++)
        #pragma unroll
        for (int r = 0; r < 4; r++) o[t][r] = 0.f;
    float lacc[4] = {0.f, 0.f, 0.f, 0.f};
    const unsigned ONES = 0x3C003C00u;    // (1.0h, 1.0h)

    for (int kb = 0; kb < 64; kb++) {
        const int st = kb & 1;
        CP_WAIT0();
        __syncthreads();

        if (kb + 1 < 64) {     // prefetch next tile, overlaps compute
            uint32_t off = (uint32_t)((st ^ 1) * KV_BYTES) + cdst;
            int s2 = (kb + 1) * 64 * 32 + csrc;
            cp16(ks_base + off, Kg + s2);
            cp16(vs_base + off, Vg + s2);
            CP_COMMIT();
        }

        const uint32_t kbase = ks_base + st * KV_BYTES;
        const uint32_t vbase = vs_base + st * KV_BYTES;

        // ---- S = Q K^T (16 x 64 per warp), log2-domain logits ----
        float s[8][4];
        #pragma unroll
        for (int t = 0; t < 8; t++) {
            unsigned b0, b1, b2, b3;
            uint32_t addr = kbase +
                (uint32_t)(((t * 8 + (lane & 7)) * PITCH + (lane >> 3) * 8) * 2);
            LDMX4(b0, b1, b2, b3, addr);
            s[t][0] = s[t][1] = s[t][2] = s[t][3] = 0.f;
            MMA16816(s[t], qa[0], b0, b1);
            MMA16816(s[t], qa[1], b2, b3);
        }

        // ---- per jc-chunk: pack -> ex2.f16x2 -> l-MMA + PV MMAs ----
        #pragma unroll
        for (int jc = 0; jc < 4; jc++) {
            unsigned pu[4];
            pu[0] = ex2h2(pack_h2(s[2*jc][0],   s[2*jc][1]));
            pu[1] = ex2h2(pack_h2(s[2*jc][2],   s[2*jc][3]));
            pu[2] = ex2h2(pack_h2(s[2*jc+1][0], s[2*jc+1][1]));
            pu[3] = ex2h2(pack_h2(s[2*jc+1][2], s[2*jc+1][3]));

            MMA16816(lacc, pu, ONES, ONES);   // row sums -> persistent fp32 acc

            uint32_t a0 = vbase +
                (uint32_t)(((jc * 16 + (lane & 15)) * PITCH + (lane >> 4) * 8) * 2);
            unsigned r0, r1, r2, r3;
            LDMX4T(r0, r1, r2, r3, a0);
            MMA16816(o[0], pu, r0, r1);
            MMA16816(o[1], pu, r2, r3);
            LDMX4T(r0, r1, r2, r3, a0 + 32);
            MMA16816(o[2], pu, r0, r1);
            MMA16816(o[3], pu, r2, r3);
        }
    }

    // ---- finalize: l broadcast across accumulator columns ----
    const int q2 = (lane & 3) * 2;
    float inv0 = 1.0f / lacc[0];
    float inv1 = 1.0f / lacc[2];

    int b = bh >> 2, h = bh & 3;
    int row0 = qt * 128 + rb + g;
    __half* dst0 = g_Oh + (b * N_ + row0) * 128 + h * 32;
    __half* dst1 = dst0 + 8 * 128;
    #pragma unroll
    for (int t = 0; t < 4; t++) {
        int d = t * 8 + q2;
        *(__half2*)&dst0[d] = __float22half2_rn(make_float2(o[t][0] * inv0, o[t][1] * inv0));
        *(__half2*)&dst1[d] = __float22half2_rn(make_float2(o[t][2] * inv1, o[t][3] * inv1));
    }
}

// =====================================================================
// Kernel 4: output projection fp16 tensor-core (Oh[16384,128] @ Wo[128,128])
// + bias, fp32 out.
// =====================================================================
__global__ __launch_bounds__(256) void gemm_out_h(
    const float* __restrict__ bias, float* __restrict__ out)
{
    __shared__ __align__(16) __half As[128][GP];
    __shared__ __align__(16) __half Bs[64][GP];
    const int nc  = blockIdx.x;       // 0..1
    const int mt  = blockIdx.y;       // 0..127
    const int tid = threadIdx.x;
    const int lane = tid & 31;
    const int warp = tid >> 5;
    const int g    = lane >> 2;
    const int q2   = (lane & 3) * 2;

    const uint32_t as_base = (uint32_t)__cvta_generic_to_shared(&As[0][0]);
    const uint32_t bs_base = (uint32_t)__cvta_generic_to_shared(&Bs[0][0]);
    const __half* Ap = g_Oh + mt * 128 * 128;
    const __half* Bp = g_Wouth + nc * 64;

    float acc[8][4];
    #pragma unroll
    for (int t = 0; t < 8; t++)
        #pragma unroll
        for (int r = 0; r < 4; r++) acc[t][r] = 0.f;

    #pragma unroll
    for (int p = 0; p < 2; p++) {
        if (p) __syncthreads();
        #pragma unroll
        for (int j = 0; j < 4; j++) {
            int i = tid + j * 256;
            int row = i >> 3, c8 = (i & 7) * 8;
            cp16(as_base + (uint32_t)((row * GP + c8) * 2),
                 Ap + row * 128 + p * 64 + c8);
        }
        #pragma unroll
        for (int j = 0; j < 2; j++) {
            int i = tid + j * 256;
            int row = i >> 3, c8 = (i & 7) * 8;
            cp16(bs_base + (uint32_t)((row * GP + c8) * 2),
                 Bp + (p * 64 + row) * 128 + c8);
        }
        CP_COMMIT(); CP_WAIT0();
        __syncthreads();

        #pragma unroll
        for (int kc = 0; kc < 4; kc++) {
            unsigned a[4];
            LDMX4(a[0], a[1], a[2], a[3], as_base +
                (uint32_t)(((warp * 16 + (lane & 15)) * GP + kc * 16 + (lane >> 4) * 8) * 2));
            #pragma unroll
            for (int t = 0; t < 4; t++) {
                unsigned b0, b1, b2, b3;
                LDMX4T(b0, b1, b2, b3, bs_base +
                    (uint32_t)(((kc * 16 + (lane & 15)) * GP + t * 16 + (lane >> 4) * 8) * 2));
                MMA16816(acc[2 * t],     a, b0, b1);
                MMA16816(acc[2 * t + 1], a, b2, b3);
            }
        }
    }

    #pragma unroll
    for (int t = 0; t < 8; t++) {
        int e = nc * 64 + t * 8 + q2;
        float2 bv = *(const float2*)&bias[e];
        #pragma unroll
        for (int half_ = 0; half_ < 2; half_++) {
            int m = mt * 128 + warp * 16 + g + half_ * 8;
            *(float2*)&out[m * 128 + e] =
                make_float2(acc[t][half_ * 2] + bv.x, acc[t][half_ * 2 + 1] + bv.y);
        }
    }
}

// =====================================================================
extern "C" void kernel_launch(void* const* d_in, const int* in_sizes, int n_in,
                              void* d_out, int out_size)
{
    const float* x     = (const float*)d_in[0];   // [4,4096,128]
    const float* Wqkv  = (const float*)d_in[1];   // [128,384]
    const float* Wout  = (const float*)d_in[2];   // [128,128]
    const float* bout  = (const float*)d_in[3];   // [128]
    float* out = (float*)d_out;                   // [4,4096,128]

    cvt_all_kernel<<<2112, 256>>>((const float4*)x, (const float4*)Wqkv,
                                  (const float4*)Wout);
    gemm_qkv_h<<<dim3(6, 128), 256>>>();
    colnorm_partial<<<256, 256>>>();
    finalize_scale<<<1, 512>>>();
    flash_kernel<<<dim3(32, 16), 256>>>();
    gemm_out_h<<<dim3(2, 128), 256>>>(bout, out);
}

// round 7
// speedup vs baseline: 2.4068x; 1.0027x over previous
#include <cuda_runtime.h>
#include <cuda_fp16.h>
#include <cstdint>

// Problem constants
#define B_   4
#define N_   4096
#define C_   128
#define H_   4
#define D_   32
#define BH_  (B_*H_)           // 16
#define QK_ELEMS (BH_*N_*D_)   // 2,097,152

// ---------------- static scratch (no allocs allowed) ----------------
__device__ __half g_Qh[QK_ELEMS];        // raw q (unnormalized) fp16
__device__ __half g_Kh[QK_ELEMS];        // raw k fp16
__device__ __half g_Vh[QK_ELEMS];
__device__ __half g_Oh[B_*N_*C_];        // attention output fp16 [b][n][h*32+d]
__device__ float  g_part[2][8][512];     // column sumsq partials [q/k][chunk][bh*32+d]

// ---------------- PTX helpers ----------------
#define MMA16816(d, a, b0, b1)                                                  \
    asm volatile("mma.sync.aligned.m16n8k16.row.col.f32.f16.f16.f32 "          \
        "{%0,%1,%2,%3}, {%4,%5,%6,%7}, {%8,%9}, {%0,%1,%2,%3};\n"              \
        : "+f"(d[0]), "+f"(d[1]), "+f"(d[2]), "+f"(d[3])                        \
        : "r"(a[0]), "r"(a[1]), "r"(a[2]), "r"(a[3]), "r"(b0), "r"(b1))

#define LDMX4(r0,r1,r2,r3,addr)                                                 \
    asm volatile("ldmatrix.sync.aligned.m8n8.x4.shared.b16 {%0,%1,%2,%3}, [%4];\n" \
        : "=r"(r0), "=r"(r1), "=r"(r2), "=r"(r3) : "r"(addr))

#define LDMX4T(r0,r1,r2,r3,addr)                                                \
    asm volatile("ldmatrix.sync.aligned.m8n8.x4.trans.shared.b16 {%0,%1,%2,%3}, [%4];\n" \
        : "=r"(r0), "=r"(r1), "=r"(r2), "=r"(r3) : "r"(addr))

__device__ __forceinline__ void cp16(uint32_t dst, const void* src) {
    asm volatile("cp.async.cg.shared.global [%0], [%1], 16;\n" :: "r"(dst), "l"(src));
}
#define CP_COMMIT() asm volatile("cp.async.commit_group;\n" ::: "memory")
#define CP_WAIT0()  asm volatile("cp.async.wait_group 0;\n" ::: "memory")

__device__ __forceinline__ unsigned pack_h2(float x, float y) {
    __half2 h = __float22half2_rn(make_float2(x, y));
    return *reinterpret_cast<unsigned*>(&h);
}
__device__ __forceinline__ unsigned ex2h2(unsigned x) {
    unsigned r; asm("ex2.approx.f16x2 %0, %1;" : "=r"(r) : "r"(x)); return r;
}

// convert 8 consecutive fp32 -> int4 of 8 halves
__device__ __forceinline__ int4 cvt8(const float* __restrict__ src) {
    float4 v0 = *(const float4*)src;
    float4 v1 = *(const float4*)(src + 4);
    __half2 h[4];
    h[0] = __float22half2_rn(make_float2(v0.x, v0.y));
    h[1] = __float22half2_rn(make_float2(v0.z, v0.w));
    h[2] = __float22half2_rn(make_float2(v1.x, v1.y));
    h[3] = __float22half2_rn(make_float2(v1.z, v1.w));
    return *(int4*)h;
}

// =====================================================================
// Kernel 1: QKV GEMM fp16 tensor-core, fp32 inputs converted in-staging.
// (X[16384,128]fp32 @ Wqkv[128,384]fp32), fp32 acc, q/k/v fp16 out
// in [bh][n][d] layout. grid (6 nc of 64, 128 mt of 128), 256 thr.
// =====================================================================
#define GP 72   // smem pitch in halves

__global__ __launch_bounds__(256) void gemm_qkv_h(
    const float* __restrict__ X, const float* __restrict__ Wq)
{
    __shared__ __align__(16) __half As[128][GP];
    __shared__ __align__(16) __half Bs[64][GP];
    const int nc  = blockIdx.x;       // 0..5
    const int mt  = blockIdx.y;       // 0..127
    const int tid = threadIdx.x;
    const int lane = tid & 31;
    const int warp = tid >> 5;
    const int g    = lane >> 2;
    const int q2   = (lane & 3) * 2;

    const uint32_t as_base = (uint32_t)__cvta_generic_to_shared(&As[0][0]);
    const uint32_t bs_base = (uint32_t)__cvta_generic_to_shared(&Bs[0][0]);

    float acc[8][4];
    #pragma unroll
    for (int t = 0; t < 8; t++)
        #pragma unroll
        for (int r = 0; r < 4; r++) acc[t][r] = 0.f;

    #pragma unroll
    for (int p = 0; p < 2; p++) {
        if (p) __syncthreads();
        #pragma unroll
        for (int j = 0; j < 4; j++) {        // A: 128x64 fp32 -> fp16
            int i = tid + j * 256;
            int row = i >> 3, c8 = (i & 7) * 8;
            *(int4*)&As[row][c8] =
                cvt8(X + (mt * 128 + row) * 128 + p * 64 + c8);
        }
        #pragma unroll
        for (int j = 0; j < 2; j++) {        // B: 64x64 fp32 -> fp16
            int i = tid + j * 256;
            int row = i >> 3, c8 = (i & 7) * 8;
            *(int4*)&Bs[row][c8] =
                cvt8(Wq + (p * 64 + row) * 384 + nc * 64 + c8);
        }
        __syncthreads();

        #pragma unroll
        for (int kc = 0; kc < 4; kc++) {
            unsigned a[4];
            LDMX4(a[0], a[1], a[2], a[3], as_base +
                (uint32_t)(((warp * 16 + (lane & 15)) * GP + kc * 16 + (lane >> 4) * 8) * 2));
            #pragma unroll
            for (int t = 0; t < 4; t++) {
                unsigned b0, b1, b2, b3;
                LDMX4T(b0, b1, b2, b3, bs_base +
                    (uint32_t)(((kc * 16 + (lane & 15)) * GP + t * 16 + (lane >> 4) * 8) * 2));
                MMA16816(acc[2 * t],     a, b0, b1);
                MMA16816(acc[2 * t + 1], a, b2, b3);
            }
        }
    }

    // epilogue: all fp16
    #pragma unroll
    for (int t = 0; t < 8; t++) {
        int e  = nc * 64 + t * 8 + q2;
        int ec = e & 127;
        int h  = ec >> 5, d = ec & 31;
        #pragma unroll
        for (int half_ = 0; half_ < 2; half_++) {
            int m = mt * 128 + warp * 16 + g + half_ * 8;
            int b = m >> 12, n = m & 4095;
            int idx = ((b * 4 + h) * 4096 + n) * 32 + d;
            __half2 hv = __float22half2_rn(
                make_float2(acc[t][half_ * 2], acc[t][half_ * 2 + 1]));
            if (nc < 2)      *(__half2*)&g_Qh[idx] = hv;
            else if (nc < 4) *(__half2*)&g_Kh[idx] = hv;
            else             *(__half2*)&g_Vh[idx] = hv;
        }
    }
}

// =====================================================================
// Kernel 2: column sum-of-squares partials (fp16 src, fp32 acc).
// grid 256 = 16 bh x {q,k} x 8 chunks of 512 rows. Deterministic.
// =====================================================================
__global__ __launch_bounds__(256) void colnorm_partial()
{
    const int bx = blockIdx.x;
    const int bh = bx & 15;
    const int r  = bx >> 4;
    const int which = r & 1;          // 0 = q, 1 = k
    const int chunk = r >> 1;         // 0..7
    const __half* src = (which ? g_Kh : g_Qh) + (bh * N_ + chunk * 512) * 32;
    const int d = threadIdx.x & 31;
    const int grp = threadIdx.x >> 5;

    float s = 0.f;
    for (int n = grp; n < 512; n += 8) {
        float v = __half2float(src[n * 32 + d]);
        s = fmaf(v, v, s);
    }
    __shared__ float red[256];
    red[threadIdx.x] = s;
    __syncthreads();
    if (threadIdx.x < 32) {
        float tot = 0.f;
        #pragma unroll
        for (int g = 0; g < 8; g++) tot += red[g * 32 + d];
        g_part[which][chunk][bh * 32 + d] = tot;
    }
}

// =====================================================================
// Kernel 3: flash attention. Scale computed in-block from g_part,
// applied at Q staging; exp via ex2.approx.f16x2; row-sum l via
// ones-MMA; 1 barrier/iter. grid (32 q-tiles of 128, 16 bh), 256 thr.
// =====================================================================
#define PITCH     40                    // halves per smem row
#define KV_BYTES  (64 * PITCH * 2)      // bytes per K or V stage

__global__ __launch_bounds__(256) void flash_kernel()
{
    const int qt   = blockIdx.x;      // 0..31
    const int bh   = blockIdx.y;      // 0..15
    const int tid  = threadIdx.x;
    const int lane = tid & 31;
    const int warp = tid >> 5;        // 0..7
    const int g    = lane >> 2;       // 0..7

    __shared__ __align__(16) __half Qs[128][PITCH];
    __shared__ __align__(16) __half Ks[2][64][PITCH];
    __shared__ __align__(16) __half Vs[2][64][PITCH];
    __shared__ float scl[32];

    const __half* Qg = g_Qh + (bh * N_ + qt * 128) * 32;
    const __half* Kg = g_Kh + bh * N_ * 32;
    const __half* Vg = g_Vh + bh * N_ * 32;

    const uint32_t qs_base = (uint32_t)__cvta_generic_to_shared(&Qs[0][0]);
    const uint32_t ks_base = (uint32_t)__cvta_generic_to_shared(&Ks[0][0][0]);
    const uint32_t vs_base = (uint32_t)__cvta_generic_to_shared(&Vs[0][0][0]);

    const int crow = tid >> 2;
    const int ccol = (tid & 3) * 8;
    const uint32_t cdst = (uint32_t)(crow * (PITCH * 2) + ccol * 2);
    const int     csrc  = crow * 32 + ccol;

    // prefetch KV tile 0
    cp16(ks_base + cdst, Kg + csrc);
    cp16(vs_base + cdst, Vg + csrc);
    CP_COMMIT();

    // per-block scale finalize (replaces finalize_scale kernel)
    if (tid < 32) {
        float qs = 0.f, ks = 0.f;
        #pragma unroll
        for (int c = 0; c < 8; c++) {
            qs += g_part[0][c][bh * 32 + tid];
            ks += g_part[1][c][bh * 32 + tid];
        }
        float qn = fmaxf(sqrtf(qs), 1e-12f);
        float kn = fmaxf(sqrtf(ks), 1e-12f);
        scl[tid] = 14.4269504088896f / (qn * kn);   // 10*log2(e)/(|q||k|)
    }
    __syncthreads();

    // stage Q (raw fp16 * fp32 scale -> fp16) while tile 0 streams
    {
        const int d0 = (tid & 3) * 8;       // constant across both chunks
        float sc[8];
        #pragma unroll
        for (int j = 0; j < 8; j++) sc[j] = scl[d0 + j];
        const int4* src = (const int4*)Qg;
        #pragma unroll
        for (int i = tid; i < 512; i += 256) {
            int4 v = src[i];
            __half2* hp = (__half2*)&v;
            #pragma unroll
            for (int j = 0; j < 4; j++) {
                float2 f = __half22float2(hp[j]);
                f.x *= sc[2 * j]; f.y *= sc[2 * j + 1];
                hp[j] = __float22half2_rn(f);
            }
            *(int4*)&Qs[i >> 2][(i & 3) * 8] = v;
        }
    }
    __syncthreads();

    // Q A-fragments for the whole loop
    unsigned qa[2][4];
    const int rb = warp * 16;
    #pragma unroll
    for (int kc = 0; kc < 2; kc++) {
        uint32_t addr = qs_base +
            (uint32_t)(((rb + (lane & 15)) * PITCH + kc * 16 + (lane >> 4) * 8) * 2);
        LDMX4(qa[kc][0], qa[kc][1], qa[kc][2], qa[kc][3], addr);
    }

    float o[4][4];
    #pragma unroll
    for (int t = 0; t < 4; t++)
        #pragma unroll
        for (int r = 0; r < 4; r++) o[t][r] = 0.f;
    float lacc[4] = {0.f, 0.f, 0.f, 0.f};
    const unsigned ONES = 0x3C003C00u;    // (1.0h, 1.0h)

    for (int kb = 0; kb < 64; kb++) {
        const int st = kb & 1;
        CP_WAIT0();
        __syncthreads();

        if (kb + 1 < 64) {     // prefetch next tile, overlaps compute
            uint32_t off = (uint32_t)((st ^ 1) * KV_BYTES) + cdst;
            int s2 = (kb + 1) * 64 * 32 + csrc;
            cp16(ks_base + off, Kg + s2);
            cp16(vs_base + off, Vg + s2);
            CP_COMMIT();
        }

        const uint32_t kbase = ks_base + st * KV_BYTES;
        const uint32_t vbase = vs_base + st * KV_BYTES;

        // ---- S = Q K^T (16 x 64 per warp), log2-domain logits ----
        float s[8][4];
        #pragma unroll
        for (int t = 0; t < 8; t++) {
            unsigned b0, b1, b2, b3;
            uint32_t addr = kbase +
                (uint32_t)(((t * 8 + (lane & 7)) * PITCH + (lane >> 3) * 8) * 2);
            LDMX4(b0, b1, b2, b3, addr);
            s[t][0] = s[t][1] = s[t][2] = s[t][3] = 0.f;
            MMA16816(s[t], qa[0], b0, b1);
            MMA16816(s[t], qa[1], b2, b3);
        }

        // ---- per jc-chunk: pack -> ex2.f16x2 -> l-MMA + PV MMAs ----
        #pragma unroll
        for (int jc = 0; jc < 4; jc++) {
            unsigned pu[4];
            pu[0] = ex2h2(pack_h2(s[2*jc][0],   s[2*jc][1]));
            pu[1] = ex2h2(pack_h2(s[2*jc][2],   s[2*jc][3]));
            pu[2] = ex2h2(pack_h2(s[2*jc+1][0], s[2*jc+1][1]));
            pu[3] = ex2h2(pack_h2(s[2*jc+1][2], s[2*jc+1][3]));

            MMA16816(lacc, pu, ONES, ONES);   // row sums -> persistent fp32 acc

            uint32_t a0 = vbase +
                (uint32_t)(((jc * 16 + (lane & 15)) * PITCH + (lane >> 4) * 8) * 2);
            unsigned r0, r1, r2, r3;
            LDMX4T(r0, r1, r2, r3, a0);
            MMA16816(o[0], pu, r0, r1);
            MMA16816(o[1], pu, r2, r3);
            LDMX4T(r0, r1, r2, r3, a0 + 32);
            MMA16816(o[2], pu, r0, r1);
            MMA16816(o[3], pu, r2, r3);
        }
    }

    // ---- finalize: l broadcast across accumulator columns ----
    const int q2 = (lane & 3) * 2;
    float inv0 = 1.0f / lacc[0];
    float inv1 = 1.0f / lacc[2];

    int b = bh >> 2, h = bh & 3;
    int row0 = qt * 128 + rb + g;
    __half* dst0 = g_Oh + (b * N_ + row0) * 128 + h * 32;
    __half* dst1 = dst0 + 8 * 128;
    #pragma unroll
    for (int t = 0; t < 4; t++) {
        int d = t * 8 + q2;
        *(__half2*)&dst0[d] = __float22half2_rn(make_float2(o[t][0] * inv0, o[t][1] * inv0));
        *(__half2*)&dst1[d] = __float22half2_rn(make_float2(o[t][2] * inv1, o[t][3] * inv1));
    }
}

// =====================================================================
// Kernel 4: output projection fp16 tensor-core
// (Oh[16384,128] @ Wout[128,128]fp32->fp16 in staging) + bias, fp32 out.
// =====================================================================
__global__ __launch_bounds__(256) void gemm_out_h(
    const float* __restrict__ Wo, const float* __restrict__ bias,
    float* __restrict__ out)
{
    __shared__ __align__(16) __half As[128][GP];
    __shared__ __align__(16) __half Bs[64][GP];
    const int nc  = blockIdx.x;       // 0..1
    const int mt  = blockIdx.y;       // 0..127
    const int tid = threadIdx.x;
    const int lane = tid & 31;
    const int warp = tid >> 5;
    const int g    = lane >> 2;
    const int q2   = (lane & 3) * 2;

    const uint32_t as_base = (uint32_t)__cvta_generic_to_shared(&As[0][0]);
    const uint32_t bs_base = (uint32_t)__cvta_generic_to_shared(&Bs[0][0]);
    const __half* Ap = g_Oh + mt * 128 * 128;

    float acc[8][4];
    #pragma unroll
    for (int t = 0; t < 8; t++)
        #pragma unroll
        for (int r = 0; r < 4; r++) acc[t][r] = 0.f;

    #pragma unroll
    for (int p = 0; p < 2; p++) {
        if (p) __syncthreads();
        #pragma unroll
        for (int j = 0; j < 4; j++) {        // A: fp16 via cp.async
            int i = tid + j * 256;
            int row = i >> 3, c8 = (i & 7) * 8;
            cp16(as_base + (uint32_t)((row * GP + c8) * 2),
                 Ap + row * 128 + p * 64 + c8);
        }
        #pragma unroll
        for (int j = 0; j < 2; j++) {        // B: fp32 -> fp16 in staging
            int i = tid + j * 256;
            int row = i >> 3, c8 = (i & 7) * 8;
            *(int4*)&Bs[row][c8] =
                cvt8(Wo + (p * 64 + row) * 128 + nc * 64 + c8);
        }
        CP_COMMIT(); CP_WAIT0();
        __syncthreads();

        #pragma unroll
        for (int kc = 0; kc < 4; kc++) {
            unsigned a[4];
            LDMX4(a[0], a[1], a[2], a[3], as_base +
                (uint32_t)(((warp * 16 + (lane & 15)) * GP + kc * 16 + (lane >> 4) * 8) * 2));
            #pragma unroll
            for (int t = 0; t < 4; t++) {
                unsigned b0, b1, b2, b3;
                LDMX4T(b0, b1, b2, b3, bs_base +
                    (uint32_t)(((kc * 16 + (lane & 15)) * GP + t * 16 + (lane >> 4) * 8) * 2));
                MMA16816(acc[2 * t],     a, b0, b1);
                MMA16816(acc[2 * t + 1], a, b2, b3);
            }
        }
    }

    #pragma unroll
    for (int t = 0; t < 8; t++) {
        int e = nc * 64 + t * 8 + q2;
        float2 bv = *(const float2*)&bias[e];
        #pragma unroll
        for (int half_ = 0; half_ < 2; half_++) {
            int m = mt * 128 + warp * 16 + g + half_ * 8;
            *(float2*)&out[m * 128 + e] =
                make_float2(acc[t][half_ * 2] + bv.x, acc[t][half_ * 2 + 1] + bv.y);
        }
    }
}

// =====================================================================
extern "C" void kernel_launch(void* const* d_in, const int* in_sizes, int n_in,
                              void* d_out, int out_size)
{
    const float* x     = (const float*)d_in[0];   // [4,4096,128]
    const float* Wqkv  = (const float*)d_in[1];   // [128,384]
    const float* Wout  = (const float*)d_in[2];   // [128,128]
    const float* bout  = (const float*)d_in[3];   // [128]
    float* out = (float*)d_out;                   // [4,4096,128]

    gemm_qkv_h<<<dim3(6, 128), 256>>>(x, Wqkv);
    colnorm_partial<<<256, 256>>>();
    flash_kernel<<<dim3(32, 16), 256>>>();
    gemm_out_h<<<dim3(2, 128), 256>>>(Wout, bout, out);
}